// round 8
// baseline (speedup 1.0000x reference)
#include <cuda_runtime.h>
#include <cuda_fp16.h>
#include <cstdint>

// ============================================================================
// Scratch (static __device__ arrays — no allocations allowed)
// ============================================================================
#define KROWS 8192
#define NROWS 8192
#define MDIM  64
#define NSPLIT 8

__device__ __half g_Xh[KROWS * MDIM];       // (2*log2e) * x, f16
__device__ __half g_Ch[NROWS * MDIM];       // x_basis, f16
__device__ __half g_xsh[KROWS];             // -log2e * ||x_i||^2  (f16)
__device__ __half g_csh[NROWS];             // -log2e * ||c_j||^2  (f16)
__device__ __half g_wh[NROWS];              // w_j                 (f16)
__device__ float  g_partial[NSPLIT][KROWS]; // j-split partial logits

#define LOG2E 1.4426950408889634f

// ============================================================================
// PTX helpers (baseline features only — sm_100 non-'a' target)
// ============================================================================
__device__ __forceinline__ uint32_t smem_u32(const void* p) {
    uint32_t a;
    asm("{ .reg .u64 t; cvta.to.shared.u64 t, %1; cvt.u32.u64 %0, t; }"
        : "=r"(a) : "l"(p));
    return a;
}

// f16 x f16 -> f16 accumulate
__device__ __forceinline__ void mma16816_f16(uint32_t& c0, uint32_t& c1,
                                             const uint32_t* a,
                                             uint32_t b0, uint32_t b1) {
    asm volatile(
        "mma.sync.aligned.m16n8k16.row.col.f16.f16.f16.f16 "
        "{%0,%1}, {%2,%3,%4,%5}, {%6,%7}, {%0,%1};"
        : "+r"(c0), "+r"(c1)
        : "r"(a[0]), "r"(a[1]), "r"(a[2]), "r"(a[3]), "r"(b0), "r"(b1));
}

__device__ __forceinline__ void ldsm_x4(uint32_t addr, uint32_t* r) {
    asm volatile("ldmatrix.sync.aligned.m8n8.x4.shared.b16 {%0,%1,%2,%3}, [%4];"
                 : "=r"(r[0]), "=r"(r[1]), "=r"(r[2]), "=r"(r[3]) : "r"(addr));
}

#define CP_ASYNC16(dst, src) \
    asm volatile("cp.async.cg.shared.global [%0], [%1], 16;" :: "r"(dst), "l"(src))
#define CP_COMMIT() asm volatile("cp.async.commit_group;" ::: "memory")
#define CP_WAIT0()  asm volatile("cp.async.wait_group 0;" ::: "memory")

__device__ __forceinline__ uint32_t ex2_h2(uint32_t t) {
    uint32_t e;
    asm("ex2.approx.f16x2 %0, %1;" : "=r"(e) : "r"(t));
    return e;
}

// ============================================================================
// K1: convert to f16 (x pre-scaled by 2*log2e), norms, cs/w pack
// ============================================================================
__global__ void prep_kernel(const float* __restrict__ x,
                            const float* __restrict__ xb,
                            const float* __restrict__ w) {
    int idx   = blockIdx.x * 256 + threadIdx.x;
    int row16 = idx >> 4;                 // 0..16383
    int s     = idx & 15;
    bool isb  = row16 >= KROWS;
    int r     = isb ? row16 - KROWS : row16;
    const float* src = isb ? xb : x;

    float4 v = ((const float4*)(src + (size_t)r * MDIM))[s];
    const float sc = isb ? 1.0f : (2.0f * LOG2E);  // pre-scale x only
    __half2 h01 = __floats2half2_rn(sc * v.x, sc * v.y);
    __half2 h23 = __floats2half2_rn(sc * v.z, sc * v.w);
    __half* dst = isb ? g_Ch : g_Xh;
    uint2 pk;
    pk.x = *(const uint32_t*)&h01;
    pk.y = *(const uint32_t*)&h23;
    ((uint2*)(dst + (size_t)r * MDIM))[s] = pk;

    float nrm = v.x * v.x + v.y * v.y + v.z * v.z + v.w * v.w;  // unscaled norm
    #pragma unroll
    for (int o = 8; o; o >>= 1) nrm += __shfl_xor_sync(0xFFFFFFFFu, nrm, o);

    if (s == 0) {
        float e = -LOG2E * nrm;
        if (isb) {
            g_csh[r] = __float2half(e);
            g_wh[r]  = __float2half(w[r]);
        } else {
            g_xsh[r] = __float2half(e);
        }
    }
}

// ============================================================================
// K2: smem-staged f16 GEMM, accumulator pre-loaded with (xs_i + cs_j)
//     -> epilogue is just ex2.f16x2 + hfma2
// grid = (64 i-tiles, 8 j-splits) = 512 CTAs, 256 threads = 8 warps
// warp grid: 4 warp-rows (32 A-rows) x 2 warp-cols (64 B-cols)
// 2 CTAs resident per SM; work-stealing at wave>=2 evens the tail
// ============================================================================
#define TI 128
#define TJ 128
#define TPC 8               // j-tiles per CTA: 8192/8/128
#define TILE_BYTES 16384    // 128 rows x 128 B (64 f16)

__device__ __forceinline__ void stage_tile(uint32_t sdst,
                                           const __half* gsrc, int tid) {
    #pragma unroll
    for (int p = 0; p < 4; p++) {
        int c   = tid + (p << 8);            // 0..1023 16B-chunks
        int row = c >> 3, ch = c & 7;
        uint32_t dst = sdst + (row << 7) + ((ch ^ (row & 7)) << 4);
        const char* src = (const char*)gsrc + (row << 7) + (ch << 4);
        CP_ASYNC16(dst, src);
    }
}

__global__ void __launch_bounds__(256, 2) rbf_main_kernel() {
    __shared__ __align__(1024) uint8_t bufs[2][TILE_BYTES];   // 32 KB
    __shared__ float red[2][TI];

    const int tid = threadIdx.x;
    const int wid = tid >> 5;
    const int lid = tid & 31;
    const int wrow = wid >> 1;           // 0..3 (32-row slice of A)
    const int wc   = wid & 1;            // 0..1 (64-col slice of B)
    const int g    = lid >> 2;           // 0..7
    const int q2   = (lid & 3) * 2;      // 0,2,4,6

    const int i0    = blockIdx.x * TI;
    const int js    = blockIdx.y;
    const int jbase = js * (TJ * TPC);

    const uint32_t sbuf0 = smem_u32(bufs[0]);
    const uint32_t sbuf1 = smem_u32(bufs[1]);

    // ---- stage A into buf1, B tile 0 into buf0 ----
    stage_tile(sbuf1, g_Xh + (size_t)i0 * MDIM, tid);
    stage_tile(sbuf0, g_Ch + (size_t)jbase * MDIM, tid);
    CP_COMMIT();
    CP_WAIT0();
    __syncthreads();

    // ---- persistent A fragments from buf1 via ldmatrix ----
    uint32_t a[2][4][4];                 // [mt][ks][reg]
    {
        const int arow_lo = (lid & 7) + ((lid >> 3) & 1) * 8;
        const int chsel   = lid >> 4;
        #pragma unroll
        for (int mt = 0; mt < 2; mt++) {
            #pragma unroll
            for (int ks = 0; ks < 4; ks++) {
                int row = wrow * 32 + mt * 16 + arow_lo;
                int ch  = ks * 2 + chsel;
                uint32_t addr = sbuf1 + (row << 7) + ((ch ^ (row & 7)) << 4);
                ldsm_x4(addr, a[mt][ks]);
            }
        }
    }
    __syncthreads();     // A reads done before buf1 reused for B(1)

    // per-thread row exponent broadcasts (f16x2)
    __half2 xsb[2][2];
    #pragma unroll
    for (int mt = 0; mt < 2; mt++)
        #pragma unroll
        for (int h = 0; h < 2; h++)
            xsb[mt][h] = __half2half2(g_xsh[i0 + wrow * 32 + mt * 16 + g + h * 8]);

    __half2 acc2[2][2];
    #pragma unroll
    for (int mt = 0; mt < 2; mt++)
        #pragma unroll
        for (int h = 0; h < 2; h++) acc2[mt][h] = __float2half2_rn(0.f);

    // B-ldmatrix lane addressing: matrix m = lid>>3, row-octet (m>>1)
    const int brow_lo = wc * 64 + ((lid >> 4) << 3) + (lid & 7);
    const int bch_lo  = (lid >> 3) & 1;

    for (int t = 0; t < TPC; t++) {
        if (t + 1 < TPC) {
            uint32_t nb = (t & 1) ? sbuf0 : sbuf1;
            stage_tile(nb, g_Ch + (size_t)(jbase + (t + 1) * TJ) * MDIM, tid);
            CP_COMMIT();
        }
        const uint32_t sb = (t & 1) ? sbuf1 : sbuf0;
        const int j0 = jbase + t * TJ + wc * 64;

        // cs/w pairs for this tile's 8 col-octets
        __half2 cs2[8], w2[8];
        #pragma unroll
        for (int nt = 0; nt < 8; nt++) {
            const int jj = j0 + nt * 8 + q2;
            cs2[nt] = *(const __half2*)(g_csh + jj);
            w2[nt]  = *(const __half2*)(g_wh + jj);
        }

        // ---- accumulator pre-load: C = xs_row + cs_col (MMA adds the rest) ----
        uint32_t c[2][8][2];
        #pragma unroll
        for (int mt = 0; mt < 2; mt++)
            #pragma unroll
            for (int nt = 0; nt < 8; nt++)
                #pragma unroll
                for (int h = 0; h < 2; h++) {
                    __half2 init = __hadd2(xsb[mt][h], cs2[nt]);
                    c[mt][nt][h] = *(const uint32_t*)&init;
                }

        #pragma unroll
        for (int ks = 0; ks < 4; ks++) {
            uint32_t b[8][2];
            #pragma unroll
            for (int ga = 0; ga < 4; ga++) {
                int row = brow_lo + ga * 16;
                int ch  = ks * 2 + bch_lo;
                uint32_t addr = sb + (row << 7) + ((ch ^ (row & 7)) << 4);
                uint32_t r[4]; ldsm_x4(addr, r);
                b[ga * 2 + 0][0] = r[0]; b[ga * 2 + 0][1] = r[1];
                b[ga * 2 + 1][0] = r[2]; b[ga * 2 + 1][1] = r[3];
            }
            #pragma unroll
            for (int nt = 0; nt < 8; nt++) {
                mma16816_f16(c[0][nt][0], c[0][nt][1], a[0][ks], b[nt][0], b[nt][1]);
                mma16816_f16(c[1][nt][0], c[1][nt][1], a[1][ks], b[nt][0], b[nt][1]);
            }
        }

        // ---- epilogue: acc += w * 2^(c)  (c already = C2*S + xs + cs <= 0) ----
        #pragma unroll
        for (int nt = 0; nt < 8; nt++) {
            #pragma unroll
            for (int mt = 0; mt < 2; mt++) {
                #pragma unroll
                for (int h = 0; h < 2; h++) {
                    uint32_t e = ex2_h2(c[mt][nt][h]);
                    acc2[mt][h] = __hfma2(*(const __half2*)&e, w2[nt], acc2[mt][h]);
                }
            }
        }

        if (t + 1 < TPC) CP_WAIT0();
        __syncthreads();
    }

    // ---- reduce: cols within quad, then across warp-cols via smem ----
    float accf[2][2];
    #pragma unroll
    for (int mt = 0; mt < 2; mt++)
        #pragma unroll
        for (int h = 0; h < 2; h++) {
            float v = __low2float(acc2[mt][h]) + __high2float(acc2[mt][h]);
            v += __shfl_xor_sync(0xFFFFFFFFu, v, 1);
            v += __shfl_xor_sync(0xFFFFFFFFu, v, 2);
            accf[mt][h] = v;
        }

    if ((lid & 3) == 0) {
        #pragma unroll
        for (int mt = 0; mt < 2; mt++)
            #pragma unroll
            for (int h = 0; h < 2; h++)
                red[wc][wrow * 32 + mt * 16 + g + h * 8] = accf[mt][h];
    }
    __syncthreads();
    if (tid < TI)
        g_partial[js][i0 + tid] = red[0][tid] + red[1][tid];
}

// ============================================================================
// K3: combine partials + bias + sigmoid
// ============================================================================
__global__ void finish_kernel(const float* __restrict__ b, float* __restrict__ out) {
    int i = blockIdx.x * 256 + threadIdx.x;
    float z = b[0];
    #pragma unroll
    for (int s = 0; s < NSPLIT; s++) z += g_partial[s][i];
    out[i] = 1.0f / (1.0f + __expf(-z));
}

// ============================================================================
// kernel_launch
// ============================================================================
extern "C" void kernel_launch(void* const* d_in, const int* in_sizes, int n_in,
                              void* d_out, int out_size) {
    const float* x  = (const float*)d_in[0];
    const float* xb = (const float*)d_in[1];
    const float* w  = (const float*)d_in[2];
    const float* b  = (const float*)d_in[3];
    float* out = (float*)d_out;

    prep_kernel<<<1024, 256>>>(x, xb, w);
    dim3 grid(KROWS / TI, NSPLIT);
    rbf_main_kernel<<<grid, 256>>>();
    finish_kernel<<<KROWS / 256, 256>>>(b, out);
}